// round 16
// baseline (speedup 1.0000x reference)
#include <cuda_runtime.h>
#include <cuda_fp16.h>
#include <stdint.h>
#include <math.h>

typedef __half hf;

#define EPSV 1e-5f
#define SCALEV 0.03125f

// ---------------- scratch ----------------
__device__ __align__(16) hf g_qAh[33554432];                   // Qt hi [path][bh][c][n]
__device__ __align__(16) hf g_kBh[33554432];                   // [Kdt; Kt] hi
__device__ __align__(16) hf g_vAh[33554432];                   // [Vd; V] hi [bh][n][k]
__device__ __align__(16) hf g_wqh[262144], g_wqdh[262144];
__device__ __align__(16) hf g_wkh[65536], g_wvh[65536], g_wkdh[65536], g_wvdh[65536];
__device__ __align__(16) hf g_woh[2097152];                    // blocked, both paths
__device__ __align__(16) float g_sp[16777216];                 // score partials
__device__ __align__(16) float g_s[2097152];
__device__ __align__(16) float g_red[4096];                    // per-tile {sum,sumsq}
__device__ int g_cnt[128];                                     // split-K tickets (self-reset)
__device__ __align__(16) hf g_ph[2097152];
__device__ __align__(16) hf g_ch[33554432];                    // ctx fp16 blocked, both paths
__device__ float g_mv[64];

// ---------------- helpers ----------------
__device__ __forceinline__ uint32_t smem_u32(const void* p){
    uint32_t a;
    asm("{ .reg .u64 t; cvta.to.shared.u64 t, %1; cvt.u32.u64 %0, t; }" : "=r"(a) : "l"(p));
    return a;
}
__device__ __forceinline__ void cp16(uint32_t sa, const void* g){
    asm volatile("cp.async.cg.shared.global [%0], [%1], 16;" :: "r"(sa), "l"(g));
}
__device__ __forceinline__ void mma16816(float* d, const uint32_t* a, const uint32_t* b){
    asm volatile("mma.sync.aligned.m16n8k16.row.col.f32.f16.f16.f32 "
        "{%0,%1,%2,%3}, {%4,%5,%6,%7}, {%8,%9}, {%0,%1,%2,%3};"
        : "+f"(d[0]),"+f"(d[1]),"+f"(d[2]),"+f"(d[3])
        : "r"(a[0]),"r"(a[1]),"r"(a[2]),"r"(a[3]),"r"(b[0]),"r"(b[1]));
}
__device__ __forceinline__ void ldsm4(uint32_t* r, uint32_t addr){
    asm volatile("ldmatrix.sync.aligned.m8n8.x4.shared.b16 {%0,%1,%2,%3}, [%4];"
        : "=r"(r[0]),"=r"(r[1]),"=r"(r[2]),"=r"(r[3]) : "r"(addr));
}
__device__ __forceinline__ void ldsm2(uint32_t* r, uint32_t addr){
    asm volatile("ldmatrix.sync.aligned.m8n8.x2.shared.b16 {%0,%1}, [%2];"
        : "=r"(r[0]),"=r"(r[1]) : "r"(addr));
}

template<int HASAL, int PITCH, int TILEB, int NKS>
__device__ __forceinline__ void mma_tile(uint32_t tbase, const uint32_t* aoff, const uint32_t* boff,
                                         float acc[4][4][4])
{
    const uint32_t tB = tbase + (1+HASAL)*TILEB;
#pragma unroll
    for (int ks = 0; ks < NKS; ++ks){
        const int kb = ks * 32;
        uint32_t bX[4][2];
#pragma unroll
        for (int nt = 0; nt < 4; ++nt) ldsm2(bX[nt], tB + boff[nt] + kb);
#pragma unroll
        for (int pass = 0; pass <= HASAL; ++pass){
            const uint32_t tAp = tbase + pass*TILEB;
            uint32_t aH[4][4];
#pragma unroll
            for (int mt = 0; mt < 4; ++mt) ldsm4(aH[mt], tAp + aoff[mt] + kb);
#pragma unroll
            for (int mt = 0; mt < 4; ++mt)
#pragma unroll
                for (int nt = 0; nt < 4; ++nt) mma16816(acc[mt][nt], aH[mt], bX[nt]);
        }
    }
}

template<int SPITCH>
__device__ __forceinline__ void stage_acc(char* dyn, float acc[4][4][4],
                                          int wm, int wn, int quad, int lane2)
{
    float* stg = reinterpret_cast<float*>(dyn);
#pragma unroll
    for (int mt = 0; mt < 4; ++mt){
        const int r = wm*64 + mt*16 + quad;
#pragma unroll
        for (int nt = 0; nt < 4; ++nt){
            const int cc = wn*32 + nt*8 + lane2;
            stg[r*SPITCH + cc]       = acc[mt][nt][0];
            stg[r*SPITCH + cc + 1]   = acc[mt][nt][1];
            stg[(r+8)*SPITCH + cc]   = acc[mt][nt][2];
            stg[(r+8)*SPITCH + cc+1] = acc[mt][nt][3];
        }
    }
}

template<int PITCH>
__device__ __forceinline__ void frag_offsets(int l, int wm, int wn, uint32_t* aoff, uint32_t* boff){
    const int li8 = l & 7, lq = (l >> 3) & 1, lh = (l >> 4) & 1;
#pragma unroll
    for (int mt = 0; mt < 4; ++mt)
        aoff[mt] = (uint32_t)((wm*64 + mt*16 + li8 + lq*8)*PITCH + lh*16);
#pragma unroll
    for (int nt = 0; nt < 4; ++nt)
        boff[nt] = (uint32_t)((wn*32 + nt*8 + li8)*PITCH + lq*16);
}

// ---------------- generic GEMM, BK=64, 3-stage single-sync pipeline ----------------
// mode 0: fp32 -> oF ; mode 1: fp16 hi -> oH ; mode 2: scores split-K partial + fused reduction
template<int HASAL>
__global__ void __launch_bounds__(256, 2) k_gemm(
    const hf* __restrict__ Ah, const hf* __restrict__ Al,
    long sA1, long sA2, long sA3, int lda,
    const hf* __restrict__ Bh, long sB1, long sB2, long sB3, int ldb,
    int K, int zm1, int zm2, int mode,
    float* __restrict__ oF, hf* __restrict__ oH,
    long sO1, long sO2, long sO3, int ldo)
{
    const int PITCH = 144, TILEB = 18432;
    extern __shared__ char dyn[];
    const uint32_t smb = smem_u32(dyn);
    const int bufB = (2+HASAL)*TILEB;
    const int tid = threadIdx.x;
    const int l = tid & 31, wid = tid >> 5;
    const int wm = wid >> 2, wn = wid & 3;
    const int quad = l >> 2, lane2 = (l & 3) * 2;
    const int z = blockIdx.z;
    const int z1 = z / zm1, zr = z % zm1;
    const int z2 = zr / zm2, z3 = zr % zm2;
    const int m0 = blockIdx.x * 128, n0 = blockIdx.y * 128;
    const long offA = z1*sA1 + z2*sA2 + z3*sA3;
    const long offB = z1*sB1 + z2*sB2 + z3*sB3;
    const long offO = z1*sO1 + z2*sO2 + z3*sO3;

    const hf* pAh = Ah + offA + (size_t)m0*lda;
    const hf* pAl = HASAL ? (Al + offA + (size_t)m0*lda) : pAh;
    const hf* pBh = Bh + offB + (size_t)n0*ldb;

    float acc[4][4][4];
#pragma unroll
    for (int a = 0; a < 4; ++a)
#pragma unroll
        for (int b = 0; b < 4; ++b)
#pragma unroll
            for (int c = 0; c < 4; ++c) acc[a][b][c] = 0.f;

    const int NC = K / 64;

    auto copy_chunk = [&](int c, int bufi){
        const hf* srcs[3];
        int lds[3];
        int nt = 0;
        srcs[nt] = pAh + c*64; lds[nt] = lda; nt++;
        if (HASAL){ srcs[nt] = pAl + c*64; lds[nt] = lda; nt++; }
        srcs[nt] = pBh + c*64; lds[nt] = ldb; nt++;
#pragma unroll
        for (int t = 0; t < 2+HASAL; ++t){
            const uint32_t sb = smb + bufi*bufB + t*TILEB;
#pragma unroll
            for (int i = 0; i < 4; ++i){
                int e = tid + i*256;
                int row = e >> 3, cc = e & 7;
                cp16(sb + row*PITCH + cc*16, srcs[t] + (size_t)row*lds[t] + cc*8);
            }
        }
    };

    copy_chunk(0, 0);
    asm volatile("cp.async.commit_group;");
    copy_chunk(1, 1);
    asm volatile("cp.async.commit_group;");

    uint32_t aoff[4], boff[4];
    frag_offsets<PITCH>(l, wm, wn, aoff, boff);

    int bufc = 0;
    for (int c = 0; c < NC; ++c){
        if (c + 1 < NC) asm volatile("cp.async.wait_group 1;");
        else            asm volatile("cp.async.wait_group 0;");
        __syncthreads();
        if (c + 2 < NC){
            int b2 = bufc + 2; if (b2 >= 3) b2 -= 3;
            copy_chunk(c+2, b2);
            asm volatile("cp.async.commit_group;");
        }
        mma_tile<HASAL, PITCH, TILEB, 4>(smb + bufc*bufB, aoff, boff, acc);
        if (++bufc == 3) bufc = 0;
    }
    __syncthreads();

    stage_acc<132>(dyn, acc, wm, wn, quad, lane2);
    __syncthreads();
    float* stg = reinterpret_cast<float*>(dyn);
    if (mode == 0){
        for (int idx = tid; idx < 4096; idx += 256){
            int r = idx >> 5, c4 = (idx & 31) * 4;
            float4 v = *reinterpret_cast<const float4*>(stg + r*132 + c4);
            *reinterpret_cast<float4*>(oF + offO + (size_t)(m0+r)*ldo + n0 + c4) = v;
        }
    } else if (mode == 1){
        for (int idx = tid; idx < 4096; idx += 256){
            int r = idx >> 5, c4 = (idx & 31) * 4;
            float4 v = *reinterpret_cast<const float4*>(stg + r*132 + c4);
            __half2 h0 = __floats2half2_rn(v.x, v.y);
            __half2 h1 = __floats2half2_rn(v.z, v.w);
            hf* p = oH + offO + (size_t)(m0+r)*ldo + n0 + c4;
            *reinterpret_cast<__half2*>(p)     = h0;
            *reinterpret_cast<__half2*>(p + 2) = h1;
        }
    } else {
        // mode 2: write raw partial, then last CTA per tile reduces all 4 slices
        for (int idx = tid; idx < 4096; idx += 256){
            int r = idx >> 5, c4 = (idx & 31) * 4;
            float4 v = *reinterpret_cast<const float4*>(stg + r*132 + c4);
            *reinterpret_cast<float4*>(oF + offO + (size_t)(m0+r)*ldo + n0 + c4) = v;
        }
        __threadfence();
        __syncthreads();
        __shared__ int lastf;
        const int tile = ((z1*16 + z2)*2 + (int)blockIdx.y)*2 + (int)blockIdx.x;
        if (tid == 0) lastf = (atomicAdd(&g_cnt[tile], 1) == 3);
        __syncthreads();
        if (lastf){
            __threadfence();
            const long offP = offO - (long)z3*sO3;
            float lsum = 0.f, lsq = 0.f;
            for (int idx = tid; idx < 4096; idx += 256){
                int r = idx >> 5, c4 = (idx & 31) * 4;
                const float* pb = oF + offP + (size_t)(m0+r)*ldo + n0 + c4;
                float4 sv = *reinterpret_cast<const float4*>(pb);
#pragma unroll
                for (int sl = 1; sl < 4; ++sl){
                    float4 v = *reinterpret_cast<const float4*>(pb + (size_t)sl*sO3);
                    sv.x += v.x; sv.y += v.y; sv.z += v.z; sv.w += v.w;
                }
                sv.x *= SCALEV; sv.y *= SCALEV; sv.z *= SCALEV; sv.w *= SCALEV;
                size_t gi = (size_t)z1*1048576 + (size_t)z2*65536 + (size_t)(m0+r)*256 + n0 + c4;
                *reinterpret_cast<float4*>(g_s + gi) = sv;
                lsum += sv.x + sv.y + sv.z + sv.w;
                lsq  += sv.x*sv.x + sv.y*sv.y + sv.z*sv.z + sv.w*sv.w;
            }
            __shared__ float sh[256], sh2[256];
            sh[tid] = lsum; sh2[tid] = lsq;
            __syncthreads();
            for (int o = 128; o; o >>= 1){
                if (tid < o){ sh[tid] += sh[tid+o]; sh2[tid] += sh2[tid+o]; }
                __syncthreads();
            }
            if (tid == 0){
                g_red[tile*2] = sh[0];
                g_red[tile*2+1] = sh2[0];
                g_cnt[tile] = 0;
            }
        }
    }
}

// ---------------- merged projection GEMM: 1-pass, 6 stages, BK=32, 3-buffer single-sync ----------------
__global__ void __launch_bounds__(256, 2) k_proj(
    const float* __restrict__ e1, const float* __restrict__ ea,
    const float* __restrict__ ed, const float* __restrict__ eb,
    const hf* __restrict__ wq, const hf* __restrict__ wqd,
    const hf* __restrict__ wk, const hf* __restrict__ wkd,
    const hf* __restrict__ wv, const hf* __restrict__ wvd,
    hf* __restrict__ qAh, hf* __restrict__ kBh, hf* __restrict__ vAh)
{
    extern __shared__ char dyn[];
    const uint32_t smb = smem_u32(dyn);
    const int tid = threadIdx.x;
    const int l = tid & 31, wid = tid >> 5;
    const int wm = wid >> 2, wn = wid & 3;
    const int quad = l >> 2, lane2 = (l & 3) * 2;
    const int z = blockIdx.z;
    const int s = z >> 4, zz = z & 15;
    const int z2 = zz >> 2, z3 = zz & 3;
    const int m0 = blockIdx.x * 128, n0 = blockIdx.y * 128;

    const float* A; const hf* W; hf* oH; long sB3; int mode; int ldo;
    switch (s){
        case 0:  A = e1; W = wq;  sB3 = 65536; mode = 3; oH = qAh;            ldo = 4096; break;
        case 1:  A = ed; W = wqd; sB3 = 65536; mode = 3; oH = qAh + 16777216; ldo = 4096; break;
        case 2:  A = eb; W = wkd; sB3 = 0;     mode = 3; oH = kBh;            ldo = 4096; break;
        case 3:  A = ea; W = wk;  sB3 = 0;     mode = 3; oH = kBh + 16777216; ldo = 4096; break;
        case 4:  A = eb; W = wvd; sB3 = 0;     mode = 1; oH = vAh;            ldo = 256;  break;
        default: A = ea; W = wv;  sB3 = 0;     mode = 1; oH = vAh + 16777216; ldo = 256;  break;
    }
    const long offA = (long)z2*4194304 + (long)z3*256;
    const long offO = (long)z2*4194304 + (long)z3*1048576;
    const float* pA = A + offA + (size_t)m0*1024;
    const hf* pBh = W + z3*sB3 + (size_t)n0*256;

    float acc[4][4][4];
#pragma unroll
    for (int a = 0; a < 4; ++a)
#pragma unroll
        for (int b = 0; b < 4; ++b)
#pragma unroll
            for (int c = 0; c < 4; ++c) acc[a][b][c] = 0.f;

    auto copyB = [&](int c, int bufi){
        const uint32_t sb = smb + bufi*20480 + 10240;
#pragma unroll
        for (int i = 0; i < 2; ++i){
            int e = tid + i*256;
            int row = e >> 2, cc = e & 3;
            cp16(sb + row*80 + cc*16, pBh + c*32 + (size_t)row*256 + cc*8);
        }
    };
    auto ldgA = [&](float4* r, int c){
        const float* base = pA + c*32;
#pragma unroll
        for (int i = 0; i < 4; ++i){
            int e = tid + 256*i;
            int row = e >> 3, cg = e & 7;
            r[i] = *reinterpret_cast<const float4*>(base + (size_t)row*1024 + cg*4);
        }
    };
    auto stsA = [&](float4* r, int bufi){
        char* tA = dyn + bufi*20480;
#pragma unroll
        for (int i = 0; i < 4; ++i){
            int e = tid + 256*i;
            int row = e >> 3, cg = e & 7;
            float4 f = r[i];
            __half2 h0 = __floats2half2_rn(f.x, f.y);
            __half2 h1 = __floats2half2_rn(f.z, f.w);
            char* p = tA + row*80 + cg*8;
            *reinterpret_cast<__half2*>(p)     = h0;
            *reinterpret_cast<__half2*>(p + 4) = h1;
        }
    };

    uint32_t aoff[4], boff[4];
    frag_offsets<80>(l, wm, wn, aoff, boff);

    const int NC = 8;
    float4 rA[4];
    ldgA(rA, 0);
    stsA(rA, 0);
    copyB(0, 0);
    asm volatile("cp.async.commit_group;");
    ldgA(rA, 1);
    stsA(rA, 1);
    copyB(1, 1);
    asm volatile("cp.async.commit_group;");
    ldgA(rA, 2);

    int bufc = 0;
    for (int c = 0; c < NC; ++c){
        if (c + 1 < NC) asm volatile("cp.async.wait_group 1;");
        else            asm volatile("cp.async.wait_group 0;");
        __syncthreads();
        if (c + 2 < NC){
            int b2 = bufc + 2; if (b2 >= 3) b2 -= 3;
            stsA(rA, b2);
            copyB(c+2, b2);
            asm volatile("cp.async.commit_group;");
            if (c + 3 < NC) ldgA(rA, c+3);
        }
        mma_tile<0, 80, 10240, 2>(smb + bufc*20480, aoff, boff, acc);
        if (++bufc == 3) bufc = 0;
    }
    __syncthreads();

    stage_acc<129>(dyn, acc, wm, wn, quad, lane2);
    __syncthreads();
    float* stg = reinterpret_cast<float*>(dyn);
    if (mode == 1){
        for (int idx = tid; idx < 16384; idx += 256){
            int r = idx >> 7, cc = idx & 127;
            oH[offO + (size_t)(m0+r)*ldo + n0 + cc] = __float2half_rn(stg[r*129 + cc]);
        }
    } else {
        for (int idx = tid; idx < 16384; idx += 256){
            int cc = idx >> 7, r = idx & 127;
            oH[offO + (size_t)(n0+cc)*ldo + m0 + r] = __float2half_rn(stg[r*129 + cc]);
        }
    }
}

// ---------------- elementwise ----------------
// merged weight conversions: y 0..5 = QKV hi-converts, y 6..7 = Wo gather-block
__global__ void __launch_bounds__(256) k_splitW(
    const float* __restrict__ Wq, const float* __restrict__ Wqd,
    const float* __restrict__ Wk, const float* __restrict__ Wkd,
    const float* __restrict__ Wv, const float* __restrict__ Wvd,
    const float* __restrict__ Wo, const float* __restrict__ Wod,
    hf* __restrict__ wqh, hf* __restrict__ wqdh,
    hf* __restrict__ wkh, hf* __restrict__ wkdh,
    hf* __restrict__ wvh, hf* __restrict__ wvdh,
    hf* __restrict__ woh)
{
    const int s = blockIdx.y;
    if (s < 6){
        const float* src; hf* dst; int n;
        switch (s){
            case 0:  src = Wq;  dst = wqh;  n = 262144; break;
            case 1:  src = Wqd; dst = wqdh; n = 262144; break;
            case 2:  src = Wk;  dst = wkh;  n = 65536;  break;
            case 3:  src = Wkd; dst = wkdh; n = 65536;  break;
            case 4:  src = Wv;  dst = wvh;  n = 65536;  break;
            default: src = Wvd; dst = wvdh; n = 65536;  break;
        }
        int i = (blockIdx.x*256 + threadIdx.x) * 4;
        if (i >= n) return;
        float4 v = *reinterpret_cast<const float4*>(src + i);
        dst[i]   = __float2half_rn(v.x);
        dst[i+1] = __float2half_rn(v.y);
        dst[i+2] = __float2half_rn(v.z);
        dst[i+3] = __float2half_rn(v.w);
    } else {
        const int path = s - 6;
        const float* sw = path ? Wod : Wo;
        int idx = blockIdx.x*256 + threadIdx.x;
        int j = idx >> 10, t = idx & 1023;
        woh[(size_t)path*1048576 + idx] =
            __float2half_rn(sw[((size_t)j<<10) + ((t & 255)<<2) + (t>>8)]);
    }
}
// fold 4 tile-partials per plane
__global__ void __launch_bounds__(32) k_moments(){
    const int p = blockIdx.x, t = threadIdx.x;
    float s = 0.f, q = 0.f;
    if (t < 4){ s = g_red[(p*4 + t)*2]; q = g_red[(p*4 + t)*2 + 1]; }
#pragma unroll
    for (int o = 2; o; o >>= 1){
        s += __shfl_xor_sync(~0u, s, o);
        q += __shfl_xor_sync(~0u, q, o);
    }
    if (t == 0){
        float m = s * (1.f/65536.f);
        g_mv[p*2] = m;
        g_mv[p*2+1] = q * (1.f/65536.f) - m*m;
    }
}
__global__ void __launch_bounds__(256) k_softmax(){
    const int pb = blockIdx.z*16 + blockIdx.y;
    const size_t rb = ((size_t)pb*256 + blockIdx.x)*256;
    const float mean = g_mv[pb*2];
    const float inv  = rsqrtf(g_mv[pb*2+1] + EPSV);
    const int tid = threadIdx.x;
    float y = (g_s[rb + tid] - mean) * inv;
    __shared__ float red[8];
    float m = y;
#pragma unroll
    for (int o = 16; o; o >>= 1) m = fmaxf(m, __shfl_xor_sync(~0u, m, o));
    if ((tid & 31) == 0) red[tid>>5] = m;
    __syncthreads();
    if (tid == 0){ float mm = red[0]; for (int i=1;i<8;++i) mm = fmaxf(mm, red[i]); red[0] = mm; }
    __syncthreads();
    float e = expf(y - red[0]);
    __syncthreads();
    float ssum = e;
#pragma unroll
    for (int o = 16; o; o >>= 1) ssum += __shfl_xor_sync(~0u, ssum, o);
    if ((tid & 31) == 0) red[tid>>5] = ssum;
    __syncthreads();
    if (tid == 0){ float t = 0.f; for (int i=0;i<8;++i) t += red[i]; red[0] = t; }
    __syncthreads();
    g_ph[rb + tid] = __float2half_rn(e / red[0]);
}

// ---------------- launch ----------------
static void* dsym(const void* s){ void* p = 0; cudaGetSymbolAddress(&p, s); return p; }

extern "C" void kernel_launch(void* const* d_in, const int* in_sizes, int n_in,
                              void* d_out, int out_size)
{
    const float* emb1     = (const float*)d_in[0];
    const float* emb_all  = (const float*)d_in[1];
    const float* embd1    = (const float*)d_in[2];
    const float* emb_alld = (const float*)d_in[3];
    const float* Wq = (const float*)d_in[4];  const float* Wqd = (const float*)d_in[5];
    const float* Wk = (const float*)d_in[6];  const float* Wv  = (const float*)d_in[7];
    const float* Wkd= (const float*)d_in[8];  const float* Wvd = (const float*)d_in[9];
    const float* Wo = (const float*)d_in[10]; const float* Wod = (const float*)d_in[11];
    float* out = (float*)d_out;

    const int SM0 = 110592;   // k_gemm<0>: 3 buf x 2 tiles x 18432
    const int SMP = 66048;    // k_proj
    cudaFuncSetAttribute(k_gemm<0>, cudaFuncAttributeMaxDynamicSharedMemorySize, SM0);
    cudaFuncSetAttribute(k_proj,    cudaFuncAttributeMaxDynamicSharedMemorySize, SMP);

#define GH(x) ((hf*)dsym(x))
    hf *qAh = GH(g_qAh);
    hf *kBh = GH(g_kBh), *vAh = GH(g_vAh);
    hf *ch = GH(g_ch), *ph = GH(g_ph), *woh = GH(g_woh);
    float* sp = (float*)dsym(g_sp);

    // weight conversions (one launch)
    k_splitW<<<dim3(4096,8),256>>>(Wq,Wqd,Wk,Wkd,Wv,Wvd,Wo,Wod,
                                   GH(g_wqh),GH(g_wqdh),GH(g_wkh),GH(g_wkdh),GH(g_wvh),GH(g_wvdh),
                                   woh);

    // projections: 1-pass, all 6 stages in one launch
    k_proj<<<dim3(32,2,96),256,SMP>>>(emb1, emb_all, embd1, emb_alld,
                                      GH(g_wqh),GH(g_wqdh),GH(g_wkh),GH(g_wkdh),GH(g_wvh),GH(g_wvdh),
                                      qAh, kBh, vAh);

    // scores: 1-pass (Q hi x K hi), split-K x4, fused reduction + moments partials
    dim3 gsc(2,2,128);
    k_gemm<0><<<gsc,256,SM0>>>(qAh,(hf*)0, 16777216,1048576,1024, 4096,
                               kBh, 16777216,1048576,1024, 4096,
                               1024, 64,4, 2,
                               sp, (hf*)0, 4194304,65536,1048576, 256);
    k_moments<<<32,32>>>();
    k_softmax<<<dim3(256,16,2),256>>>();

    // ctx: 1-pass (V hi x probs hi), both paths in one launch
    dim3 gc(32,2,32);
    k_gemm<0><<<gc,256,SM0>>>(vAh,(hf*)0, 16777216,4194304,1048576, 256,
                              ph, 1048576,262144,65536, 256,
                              256, 16,4, 1,
                              (float*)0, ch, 16777216,4194304,256, 1024);

    // out: 1-pass (ctx hi x Wo hi), both paths in one launch
    dim3 go(128,8,2);
    k_gemm<0><<<go,256,SM0>>>(ch,(hf*)0, 16777216,0,0, 1024,
                              woh, 1048576,0,0, 1024,
                              1024, 1,1, 0,
                              out, (hf*)0, 16777216,0,0, 1024);
#undef GH
}